// round 16
// baseline (speedup 1.0000x reference)
#include <cuda_runtime.h>
#include <cuda_fp16.h>
#include <math.h>

// Persistent device scratch (no allocation allowed in kernel_launch).
__device__ __align__(16) __half g_score_h[100032];   // fp16 score table

#define NS_BLOCKS 148
#define NS_THREADS 512

// ---- packed f32x2 helpers (sm_100+; doubles fp32 FMA issue density) -------
__device__ __forceinline__ unsigned long long ffma2(unsigned long long a,
                                                    unsigned long long b,
                                                    unsigned long long c) {
    unsigned long long d;
    asm("fma.rn.f32x2 %0, %1, %2, %3;" : "=l"(d) : "l"(a), "l"(b), "l"(c));
    return d;
}
__device__ __forceinline__ unsigned long long pack2(float x, float y) {
    unsigned long long r;
    asm("mov.b64 %0, {%1, %2};" : "=l"(r) : "f"(x), "f"(y));
    return r;
}
__device__ __forceinline__ void unpack2(unsigned long long p, float& x, float& y) {
    asm("mov.b64 {%0, %1}, %2;" : "=f"(x), "=f"(y) : "l"(p));
}

// ---------------------------------------------------------------------------
// Kernel 1: persistent node-score kernel (148 blocks, no wave tail).
// Layer 2 via packed f32x2 FMA: W2 staged TRANSPOSED so one ulonglong2
// (LDS.128) gives weight pairs for outputs (j, j+1); layer 3 is applied
// while draining the packed accumulators (h2 never materializes).
// Master node: setup pins it at node 0; serial fallback scan keeps
// correctness for arbitrary inputs (never taken on bench data).
// ---------------------------------------------------------------------------
__global__ void __launch_bounds__(NS_THREADS, 1)
node_score_kernel(const float* __restrict__ x_t,
                  const float* __restrict__ x_t_dt,
                  const float* __restrict__ W1,
                  const float* __restrict__ b1,
                  const float* __restrict__ W2,
                  const float* __restrict__ b2,
                  const float* __restrict__ W3,
                  const float* __restrict__ b3,
                  int n_nodes) {
    __shared__ float sW1[96];
    __shared__ float sb1[32];
    __shared__ __align__(16) float sW2t[1024];    // transposed: [k][j]
    __shared__ __align__(16) float sb2[32];
    __shared__ float sW3[32];
    __shared__ float sb3;
    __shared__ float smx, smy, smz;
    __shared__ __align__(16) float sx[NS_THREADS * 7];
    __shared__ __align__(16) float sxd[NS_THREADS * 7];

    int t = threadIdx.x;

    for (int k = t; k < 96; k += NS_THREADS) sW1[k] = W1[k];
    // transpose while staging: sW2t[k*32 + j] = W2[j*32 + k]
    for (int idx = t; idx < 1024; idx += NS_THREADS) {
        int j = idx >> 5, k = idx & 31;
        sW2t[k * 32 + j] = W2[idx];
    }
    if (t < 32) {
        sb1[t] = b1[t];
        sb2[t] = b2[t];
        sW3[t] = W3[t];
    }
    if (t == 0) {
        sb3 = b3[0];
        if (__ldg(&x_t[0]) == 1.0f) {           // fast path: master is node 0
            smx = __ldg(&x_t[1]);
            smy = __ldg(&x_t[2]);
            smz = __ldg(&x_t[3]);
        } else {                                 // fallback (never taken)
            for (int i = 1; i < n_nodes; i++) {
                if (__ldg(&x_t[(size_t)i * 7]) == 1.0f) {
                    smx = __ldg(&x_t[(size_t)i * 7 + 1]);
                    smy = __ldg(&x_t[(size_t)i * 7 + 2]);
                    smz = __ldg(&x_t[(size_t)i * 7 + 3]);
                    break;
                }
            }
        }
    }

    int npb = (n_nodes + NS_BLOCKS - 1) / NS_BLOCKS;
    int node_beg = blockIdx.x * npb;
    int node_end = min(node_beg + npb, n_nodes);

    for (int base = node_beg; base < node_end; base += NS_THREADS) {
        int nrows = min(NS_THREADS, node_end - base);
        int nflt = nrows * 7;
        const float* xr  = x_t    + (size_t)base * 7;
        const float* xdr = x_t_dt + (size_t)base * 7;
        for (int k = t; k < nflt; k += NS_THREADS) {
            sx[k]  = xr[k];
            sxd[k] = xdr[k];
        }
        __syncthreads();

        if (t < nrows) {
            float px = sx[t * 7 + 1];
            float py = sx[t * 7 + 2];
            float pz = sx[t * 7 + 3];
            float dx = sxd[t * 7 + 1] - px;
            float dy = sxd[t * 7 + 2] - py;
            float dz = sxd[t * 7 + 3] - pz;

            float dn = sqrtf(dx * dx + dy * dy + dz * dz);  // velocity_score
            float inv_dn = 1.0f / fmaxf(dn, 1e-12f);        // dt = 1
            float vx = dx * inv_dn, vy = dy * inv_dn, vz = dz * inv_dn;

            float rx = px - smx, ry = py - smy, rz = pz - smz;
            float rn = sqrtf(rx * rx + ry * ry + rz * rz);
            float dist = rn + 1e-6f;
            float na = fmaxf(rn, 1e-6f);
            float nb = fmaxf(sqrtf(vx * vx + vy * vy + vz * vz), 1e-6f);
            float dir_score = (rx * vx + ry * vy + rz * vz) / (na * nb);

            float a0 = 1.0f / dist;
            float a1 = dir_score;
            float a2 = dn;

            // Layer 1: 3 -> 32
            float h[32];
#pragma unroll
            for (int j = 0; j < 32; j++) {
                float s = fmaf(a2, sW1[j * 3 + 2],
                         fmaf(a1, sW1[j * 3 + 1],
                         fmaf(a0, sW1[j * 3 + 0], sb1[j])));
                h[j] = fmaxf(s, 0.0f);
            }

            // Layer 2: 32 -> 32 in packed f32x2 (acc[q] = outputs 2q,2q+1).
            unsigned long long acc[16];
            const unsigned long long* b2p =
                reinterpret_cast<const unsigned long long*>(sb2);
#pragma unroll
            for (int q = 0; q < 16; q++) acc[q] = b2p[q];

            const ulonglong2* w2q = reinterpret_cast<const ulonglong2*>(sW2t);
#pragma unroll
            for (int k = 0; k < 32; k++) {
                unsigned long long hk2 = pack2(h[k], h[k]);
#pragma unroll
                for (int q = 0; q < 8; q++) {   // outputs j = 4q .. 4q+3
                    ulonglong2 w = w2q[k * 8 + q];
                    acc[2 * q]     = ffma2(hk2, w.x, acc[2 * q]);
                    acc[2 * q + 1] = ffma2(hk2, w.y, acc[2 * q + 1]);
                }
            }

            // Drain: ReLU + layer 3 dot, then sigmoid.
            float s3 = sb3;
#pragma unroll
            for (int q = 0; q < 16; q++) {
                float lo, hi;
                unpack2(acc[q], lo, hi);
                s3 = fmaf(fmaxf(lo, 0.0f), sW3[2 * q], s3);
                s3 = fmaf(fmaxf(hi, 0.0f), sW3[2 * q + 1], s3);
            }
            float sig = 1.0f / (1.0f + __expf(-s3));
            g_score_h[base + t] = __float2half(sig);
        }
        __syncthreads();
    }
}

// ---------------------------------------------------------------------------
// Kernel 2: persistent gather — byte-identical to R15 (best measured total).
// ---------------------------------------------------------------------------
#define G_THREADS 1024
__global__ void __launch_bounds__(G_THREADS, 1)
gather_kernel(const int* __restrict__ tgt,
              float* __restrict__ out,
              int n_edges, int n_nodes) {
    extern __shared__ __align__(16) __half stab[];

    int t = threadIdx.x;
    int n4 = n_edges >> 2;
    int stride = gridDim.x * G_THREADS;
    const int4* tv = reinterpret_cast<const int4*>(tgt);
    float4* ov = reinterpret_cast<float4*>(out);

    // Prefetch this thread's first index group (latency hides under copy).
    int j0 = blockIdx.x * G_THREADS + t;
    int4 a0;
    bool have0 = (j0 < n4);
    if (have0) a0 = __ldg(&tv[j0]);

    // Cooperative table load (uint4 = 8 halves, coalesced).
    int n8 = (n_nodes + 7) >> 3;
    const uint4* src = reinterpret_cast<const uint4*>(g_score_h);
    uint4* dst = reinterpret_cast<uint4*>(stab);
    for (int k = t; k < n8; k += G_THREADS) dst[k] = src[k];
    __syncthreads();

    if (have0) {
        float4 o;
        o.x = __half2float(stab[a0.x]);
        o.y = __half2float(stab[a0.y]);
        o.z = __half2float(stab[a0.z]);
        o.w = __half2float(stab[a0.w]);
        __stcs(&ov[j0], o);
    }

    for (int j = j0 + stride; j < n4; j += stride) {
        int4 a = __ldg(&tv[j]);
        float4 o;
        o.x = __half2float(stab[a.x]);
        o.y = __half2float(stab[a.y]);
        o.z = __half2float(stab[a.z]);
        o.w = __half2float(stab[a.w]);
        __stcs(&ov[j], o);
    }

    if (blockIdx.x == 0 && t == 0) {
        for (int e = n4 << 2; e < n_edges; e++)
            out[e] = __half2float(stab[__ldg(&tgt[e])]);
    }
}

extern "C" void kernel_launch(void* const* d_in, const int* in_sizes, int n_in,
                              void* d_out, int out_size) {
    const float* x_t    = (const float*)d_in[0];
    const float* x_t_dt = (const float*)d_in[1];
    const int*   edge_index = (const int*)d_in[2];   // int32 (JAX x64 off)
    const float* W1 = (const float*)d_in[3];
    const float* b1 = (const float*)d_in[4];
    const float* W2 = (const float*)d_in[5];
    const float* b2 = (const float*)d_in[6];
    const float* W3 = (const float*)d_in[7];
    const float* b3 = (const float*)d_in[8];
    float* out = (float*)d_out;

    int n_nodes = in_sizes[0] / 7;
    int n_edges = in_sizes[2] / 2;
    const int* tgt = edge_index + n_edges;  // row 1 of (2, E)

    // Kernel 1: persistent node scores (packed f32x2 layer 2).
    node_score_kernel<<<NS_BLOCKS, NS_THREADS>>>(
        x_t, x_t_dt, W1, b1, W2, b2, W3, b3, n_nodes);

    // Kernel 2: persistent gather with SMEM-resident fp16 table.
    size_t smem = ((size_t)(n_nodes + 7) & ~7ull) * sizeof(__half) + 16;
    cudaFuncSetAttribute(gather_kernel,
                         cudaFuncAttributeMaxDynamicSharedMemorySize,
                         (int)smem);
    gather_kernel<<<148, G_THREADS, smem>>>(tgt, out, n_edges, n_nodes);
}

// round 17
// speedup vs baseline: 1.0154x; 1.0154x over previous
#include <cuda_runtime.h>
#include <cuda_fp16.h>
#include <math.h>

// Persistent device scratch (no allocation allowed in kernel_launch).
__device__ __align__(16) __half g_score_h[100032];   // fp16 score table

#define NS_BLOCKS 148
#define NS_THREADS 512

// ---------------------------------------------------------------------------
// Kernel 1: persistent node-score kernel (148 blocks, no wave tail) — R15
// form (best measured) with vectorized staging: the block's 2x nrows*7-float
// row copies are float4 loads/stores (4x fewer LDG/STS issue slots), scalar
// only for the %4 tail. MLP: 3->32->32->1, layer 3 folded into layer-2 loop.
// Master node: setup pins it at node 0; serial fallback scan keeps
// correctness for arbitrary inputs (never taken on bench data).
// ---------------------------------------------------------------------------
__global__ void __launch_bounds__(NS_THREADS, 1)
node_score_kernel(const float* __restrict__ x_t,
                  const float* __restrict__ x_t_dt,
                  const float* __restrict__ W1,
                  const float* __restrict__ b1,
                  const float* __restrict__ W2,
                  const float* __restrict__ b2,
                  const float* __restrict__ W3,
                  const float* __restrict__ b3,
                  int n_nodes) {
    __shared__ float sW1[96];
    __shared__ float sb1[32];
    __shared__ __align__(16) float sW2[1024];
    __shared__ float sb2[32];
    __shared__ float sW3[32];
    __shared__ float sb3;
    __shared__ float smx, smy, smz;
    __shared__ __align__(16) float sx[NS_THREADS * 7];
    __shared__ __align__(16) float sxd[NS_THREADS * 7];

    int t = threadIdx.x;

    for (int k = t; k < 96; k += NS_THREADS) sW1[k] = W1[k];
    for (int k = t; k < 1024; k += NS_THREADS) sW2[k] = W2[k];
    if (t < 32) {
        sb1[t] = b1[t];
        sb2[t] = b2[t];
        sW3[t] = W3[t];
    }
    if (t == 0) {
        sb3 = b3[0];
        if (__ldg(&x_t[0]) == 1.0f) {           // fast path: master is node 0
            smx = __ldg(&x_t[1]);
            smy = __ldg(&x_t[2]);
            smz = __ldg(&x_t[3]);
        } else {                                 // fallback (never taken)
            for (int i = 1; i < n_nodes; i++) {
                if (__ldg(&x_t[(size_t)i * 7]) == 1.0f) {
                    smx = __ldg(&x_t[(size_t)i * 7 + 1]);
                    smy = __ldg(&x_t[(size_t)i * 7 + 2]);
                    smz = __ldg(&x_t[(size_t)i * 7 + 3]);
                    break;
                }
            }
        }
    }

    int npb = (n_nodes + NS_BLOCKS - 1) / NS_BLOCKS;
    int node_beg = blockIdx.x * npb;
    int node_end = min(node_beg + npb, n_nodes);

    for (int base = node_beg; base < node_end; base += NS_THREADS) {
        int nrows = min(NS_THREADS, node_end - base);
        int nflt = nrows * 7;
        const float* xr  = x_t    + (size_t)base * 7;
        const float* xdr = x_t_dt + (size_t)base * 7;

        // Vectorized staging: float4 main body + scalar tail.
        // (xr/xdr are 4B-aligned at worst; rely on alignment of base*7*4
        //  relative to the 16B-aligned input buffers: base*28 % 16 != 0 in
        //  general, so use per-element vector loads only when aligned.)
        if ((((size_t)xr | (size_t)xdr) & 15) == 0) {
            int nv4 = nflt >> 2;
            const float4* xr4  = reinterpret_cast<const float4*>(xr);
            const float4* xdr4 = reinterpret_cast<const float4*>(xdr);
            float4* sx4  = reinterpret_cast<float4*>(sx);
            float4* sxd4 = reinterpret_cast<float4*>(sxd);
            for (int k = t; k < nv4; k += NS_THREADS) {
                sx4[k]  = xr4[k];
                sxd4[k] = xdr4[k];
            }
            for (int k = (nv4 << 2) + t; k < nflt; k += NS_THREADS) {
                sx[k]  = xr[k];
                sxd[k] = xdr[k];
            }
        } else {
            for (int k = t; k < nflt; k += NS_THREADS) {
                sx[k]  = xr[k];
                sxd[k] = xdr[k];
            }
        }
        __syncthreads();

        if (t < nrows) {
            float px = sx[t * 7 + 1];
            float py = sx[t * 7 + 2];
            float pz = sx[t * 7 + 3];
            float dx = sxd[t * 7 + 1] - px;
            float dy = sxd[t * 7 + 2] - py;
            float dz = sxd[t * 7 + 3] - pz;

            float dn = sqrtf(dx * dx + dy * dy + dz * dz);  // velocity_score
            float inv_dn = 1.0f / fmaxf(dn, 1e-12f);        // dt = 1
            float vx = dx * inv_dn, vy = dy * inv_dn, vz = dz * inv_dn;

            float rx = px - smx, ry = py - smy, rz = pz - smz;
            float rn = sqrtf(rx * rx + ry * ry + rz * rz);
            float dist = rn + 1e-6f;
            float na = fmaxf(rn, 1e-6f);
            float nb = fmaxf(sqrtf(vx * vx + vy * vy + vz * vz), 1e-6f);
            float dir_score = (rx * vx + ry * vy + rz * vz) / (na * nb);

            float a0 = 1.0f / dist;
            float a1 = dir_score;
            float a2 = dn;

            float h[32];
#pragma unroll
            for (int j = 0; j < 32; j++) {
                float s = fmaf(a2, sW1[j * 3 + 2],
                         fmaf(a1, sW1[j * 3 + 1],
                         fmaf(a0, sW1[j * 3 + 0], sb1[j])));
                h[j] = fmaxf(s, 0.0f);
            }

            const float4* w2v = reinterpret_cast<const float4*>(sW2);
            float s3 = sb3;
#pragma unroll
            for (int j = 0; j < 32; j++) {
                float s = sb2[j];
#pragma unroll
                for (int k4 = 0; k4 < 8; k4++) {
                    float4 w = w2v[j * 8 + k4];
                    s = fmaf(h[k4 * 4 + 0], w.x, s);
                    s = fmaf(h[k4 * 4 + 1], w.y, s);
                    s = fmaf(h[k4 * 4 + 2], w.z, s);
                    s = fmaf(h[k4 * 4 + 3], w.w, s);
                }
                s3 = fmaf(fmaxf(s, 0.0f), sW3[j], s3);
            }
            float sig = 1.0f / (1.0f + __expf(-s3));
            g_score_h[base + t] = __float2half(sig);
        }
        __syncthreads();
    }
}

// ---------------------------------------------------------------------------
// Kernel 2: persistent gather — byte-identical to R15 (best measured total).
// ---------------------------------------------------------------------------
#define G_THREADS 1024
__global__ void __launch_bounds__(G_THREADS, 1)
gather_kernel(const int* __restrict__ tgt,
              float* __restrict__ out,
              int n_edges, int n_nodes) {
    extern __shared__ __align__(16) __half stab[];

    int t = threadIdx.x;
    int n4 = n_edges >> 2;
    int stride = gridDim.x * G_THREADS;
    const int4* tv = reinterpret_cast<const int4*>(tgt);
    float4* ov = reinterpret_cast<float4*>(out);

    // Prefetch this thread's first index group (latency hides under copy).
    int j0 = blockIdx.x * G_THREADS + t;
    int4 a0;
    bool have0 = (j0 < n4);
    if (have0) a0 = __ldg(&tv[j0]);

    // Cooperative table load (uint4 = 8 halves, coalesced).
    int n8 = (n_nodes + 7) >> 3;
    const uint4* src = reinterpret_cast<const uint4*>(g_score_h);
    uint4* dst = reinterpret_cast<uint4*>(stab);
    for (int k = t; k < n8; k += G_THREADS) dst[k] = src[k];
    __syncthreads();

    if (have0) {
        float4 o;
        o.x = __half2float(stab[a0.x]);
        o.y = __half2float(stab[a0.y]);
        o.z = __half2float(stab[a0.z]);
        o.w = __half2float(stab[a0.w]);
        __stcs(&ov[j0], o);
    }

    for (int j = j0 + stride; j < n4; j += stride) {
        int4 a = __ldg(&tv[j]);
        float4 o;
        o.x = __half2float(stab[a.x]);
        o.y = __half2float(stab[a.y]);
        o.z = __half2float(stab[a.z]);
        o.w = __half2float(stab[a.w]);
        __stcs(&ov[j], o);
    }

    if (blockIdx.x == 0 && t == 0) {
        for (int e = n4 << 2; e < n_edges; e++)
            out[e] = __half2float(stab[__ldg(&tgt[e])]);
    }
}

extern "C" void kernel_launch(void* const* d_in, const int* in_sizes, int n_in,
                              void* d_out, int out_size) {
    const float* x_t    = (const float*)d_in[0];
    const float* x_t_dt = (const float*)d_in[1];
    const int*   edge_index = (const int*)d_in[2];   // int32 (JAX x64 off)
    const float* W1 = (const float*)d_in[3];
    const float* b1 = (const float*)d_in[4];
    const float* W2 = (const float*)d_in[5];
    const float* b2 = (const float*)d_in[6];
    const float* W3 = (const float*)d_in[7];
    const float* b3 = (const float*)d_in[8];
    float* out = (float*)d_out;

    int n_nodes = in_sizes[0] / 7;
    int n_edges = in_sizes[2] / 2;
    const int* tgt = edge_index + n_edges;  // row 1 of (2, E)

    // Kernel 1: persistent node scores.
    node_score_kernel<<<NS_BLOCKS, NS_THREADS>>>(
        x_t, x_t_dt, W1, b1, W2, b2, W3, b3, n_nodes);

    // Kernel 2: persistent gather with SMEM-resident fp16 table.
    size_t smem = ((size_t)(n_nodes + 7) & ~7ull) * sizeof(__half) + 16;
    cudaFuncSetAttribute(gather_kernel,
                         cudaFuncAttributeMaxDynamicSharedMemorySize,
                         (int)smem);
    gather_kernel<<<148, G_THREADS, smem>>>(tgt, out, n_edges, n_nodes);
}